// round 4
// baseline (speedup 1.0000x reference)
#include <cuda_runtime.h>

// CrossAttentionConditionInjection — analytic collapse, single persistent kernel.
//
// K/V come from one condition token broadcast across seq: all scores in a row
// are equal => softmax weights are exactly 1/S (S=2048, a power of two)
// => attn == v1 broadcast. Entire op:
//   out[b,s,:] = Wo @ (Wv @ cond[b] + bv) + bo     for every s.
//
// Evidence (R1/R2): three tiny kernels pinned at exactly 12.288us = 3 x 4.096us
// regardless of kernel internals -> fixed per-node replay cost dominates.
// Fuse all phases into ONE kernel with a grid-wide ticket barrier.

#define BDIM 1024   // D
#define NB   2      // B
#define NS   2048   // S
#define GRID 128    // <= SM count (B200: 148) -> co-resident at 1 block/SM
#define TPB  1024

__device__ float    g_v1[NB * BDIM];
__device__ float    g_o1[NB * BDIM];
__device__ unsigned g_bar = 0;      // monotonic ticket counter (replay-safe)

// Grid-wide barrier: monotonic generations, deterministic across graph
// replays. nanosleep backoff keeps the poll light and guarantees progress.
__device__ __forceinline__ void grid_sync() {
    __syncthreads();
    if (threadIdx.x == 0) {
        __threadfence();                                // publish block's writes
        unsigned ticket = atomicAdd(&g_bar, 1u);
        unsigned target = (ticket / GRID + 1u) * GRID;  // end of this generation
        while (atomicAdd(&g_bar, 0u) < target)
            __nanosleep(64);
        __threadfence();                                // acquire others' writes
    }
    __syncthreads();
}

// y[b*D+d] = dot(W[d,:], x[b,:]) + bias[d].
// 2048 rows, 4096 warps -> 2 warps per row, each covering a 2KB half-row
// (4 float4 per lane), partials combined through smem.
__device__ __forceinline__ void matvec_phase(const float* __restrict__ W,
                                             const float* __restrict__ x,
                                             const float* __restrict__ bias,
                                             float* __restrict__ y,
                                             float* __restrict__ s_part) {
    int warp = threadIdx.x >> 5;               // 0..31
    int lane = threadIdx.x & 31;
    int pair = warp >> 1;                      // 0..15 : row-task within block
    int half = warp & 1;                       // which half of the row
    int t    = blockIdx.x + GRID * pair;       // 0..2047
    int b    = t >> 10;
    int d    = t & (BDIM - 1);

    const float4* W4 = reinterpret_cast<const float4*>(W + (size_t)d * BDIM)
                       + half * 128;
    const float4* x4 = reinterpret_cast<const float4*>(x + (size_t)b * BDIM)
                       + half * 128;
    float sum = 0.f;
#pragma unroll
    for (int i = 0; i < 4; ++i) {              // 4 x 512B warp-span = 2KB
        float4 wv = W4[lane + i * 32];
        float4 xv = x4[lane + i * 32];
        sum += wv.x * xv.x + wv.y * xv.y + wv.z * xv.z + wv.w * xv.w;
    }
#pragma unroll
    for (int off = 16; off; off >>= 1)
        sum += __shfl_xor_sync(0xffffffffu, sum, off);
    if (lane == 0) s_part[warp] = sum;
    __syncthreads();
    if (lane == 0 && half == 0)
        y[t] = s_part[warp] + s_part[warp + 1] + bias[d];
}

__global__ void __launch_bounds__(TPB, 1)
fused_kernel(const float* __restrict__ Wv, const float* __restrict__ cond,
             const float* __restrict__ bv, const float* __restrict__ Wo,
             const float* __restrict__ bo, float4* __restrict__ out) {
    __shared__ float  s_part[32];
    __shared__ float4 s_o1[NB * BDIM / 4];     // 8 KB broadcast staging

    // Phase 1: v1 = Wv @ cond + bv
    matvec_phase(Wv, cond, bv, g_v1, s_part);
    grid_sync();

    // Phase 2: o1 = Wo @ v1 + bo
    matvec_phase(Wo, g_v1, bo, g_o1, s_part);
    grid_sync();

    // Phase 3: out[b,s,:] = o1[b,:]. Stage o1 in smem, then 8 perfectly
    // coalesced float4 stores per thread (2^20 total / 131072 threads).
    if (threadIdx.x < NB * BDIM / 4)
        s_o1[threadIdx.x] = reinterpret_cast<const float4*>(g_o1)[threadIdx.x];
    __syncthreads();

    const int total = NB * NS * BDIM / 4;      // 2^20 float4
#pragma unroll
    for (int k = 0; k < total / (GRID * TPB); ++k) {
        int i  = (blockIdx.x * TPB + threadIdx.x) + k * (GRID * TPB);
        int b  = i >> 19;                      // / (S*D/4)
        int d4 = i & 255;                      // % (D/4)
        out[i] = s_o1[(b << 8) + d4];
    }
}

extern "C" void kernel_launch(void* const* d_in, const int* in_sizes, int n_in,
                              void* d_out, int out_size) {
    // metadata order: hidden_states, condition, Wq, bq, Wk, bk, Wv, bv, Wo, bo
    const float* cond = (const float*)d_in[1];
    const float* Wv   = (const float*)d_in[6];
    const float* bv   = (const float*)d_in[7];
    const float* Wo   = (const float*)d_in[8];
    const float* bo   = (const float*)d_in[9];

    fused_kernel<<<GRID, TPB>>>(Wv, cond, bv, Wo, bo, (float4*)d_out);
}